// round 9
// baseline (speedup 1.0000x reference)
#include <cuda_runtime.h>
#include <cuda_fp16.h>
#include <stdint.h>

#define NSPK 256
#define MUTT 64
#define DDIM 1024
#define NROWS (NSPK*MUTT)   // 16384

// ---------------- device scratch (no dynamic allocation allowed) ---------
__device__ __half g_a[(size_t)NROWS * DDIM];     // 32 MB  (A, fp16)
__device__ __half g_b[NSPK * DDIM];              // 512 KB (B, fp16)
__device__ float  g_psum[8 * NSPK * DDIM];       // 8 MB (8 partials/speaker)
__device__ float  g_q[NROWS];
__device__ float  g_L[NSPK];
__device__ float  g_L2[NSPK];

// ---------------- helpers -------------------------------------------------
static __device__ __forceinline__ uint32_t smem_u32(const void* p) {
    uint32_t a;
    asm("{ .reg .u64 t; cvta.to.shared.u64 t, %1; cvt.u32.u64 %0, t; }" : "=r"(a) : "l"(p));
    return a;
}
static __device__ __forceinline__ void cp16(uint32_t d, const void* s) {
    asm volatile("cp.async.cg.shared.global [%0], [%1], 16;\n" :: "r"(d), "l"(s));
}
static __device__ __forceinline__ void cp_commit() {
    asm volatile("cp.async.commit_group;\n" ::: "memory");
}
template <int N> static __device__ __forceinline__ void cp_wait() {
    asm volatile("cp.async.wait_group %0;\n" :: "n"(N) : "memory");
}
static __device__ __forceinline__ void ldsm4(uint32_t* r, uint32_t addr) {
    asm volatile("ldmatrix.sync.aligned.m8n8.x4.shared.b16 {%0,%1,%2,%3}, [%4];"
                 : "=r"(r[0]), "=r"(r[1]), "=r"(r[2]), "=r"(r[3]) : "r"(addr));
}
static __device__ __forceinline__ void mma_f16(float* d, const uint32_t* a, const uint32_t* b) {
    asm volatile("mma.sync.aligned.m16n8k16.row.col.f32.f16.f16.f32 "
                 "{%0,%1,%2,%3}, {%4,%5,%6,%7}, {%8,%9}, {%0,%1,%2,%3};"
                 : "+f"(d[0]), "+f"(d[1]), "+f"(d[2]), "+f"(d[3])
                 : "r"(a[0]), "r"(a[1]), "r"(a[2]), "r"(a[3]), "r"(b[0]), "r"(b[1]));
}

// ======================= K1: stats + fp16 A plane =========================
// 2048 blocks: 8 per speaker, 8 rows each. All 8 row-loads issued up front
// (MLP=8) so the dependent shfl/convert chains overlap the memory latency.
__global__ void __launch_bounds__(256) k1_stats(const float* __restrict__ in) {
    int bid = blockIdx.x;
    int spk = bid >> 3, part = bid & 7;
    int tid = threadIdx.x, w = tid >> 5, l = tid & 31;
    __shared__ float qp[8][8];

    size_t rowbase = ((size_t)spk * MUTT + part * 8) * DDIM;
    const float4* src = (const float4*)(in + rowbase);

    float4 v[8];
    #pragma unroll
    for (int r = 0; r < 8; r++) v[r] = src[r * (DDIM / 4) + tid];

    float c0 = 0.f, c1 = 0.f, c2 = 0.f, c3 = 0.f;
    float qv[8];
    #pragma unroll
    for (int r = 0; r < 8; r++) {
        c0 += v[r].x; c1 += v[r].y; c2 += v[r].z; c3 += v[r].w;
        qv[r] = v[r].x * v[r].x + v[r].y * v[r].y + v[r].z * v[r].z + v[r].w * v[r].w;

        union { __half2 h2[2]; uint2 u; } ph;
        ph.h2[0] = __floats2half2_rn(v[r].x, v[r].y);
        ph.h2[1] = __floats2half2_rn(v[r].z, v[r].w);
        *(uint2*)(g_a + rowbase + (size_t)r * DDIM + (size_t)tid * 4) = ph.u;
    }
    // independent shfl trees for the 8 rows (no serial chain between rows)
    #pragma unroll
    for (int r = 0; r < 8; r++) {
        float q = qv[r];
        #pragma unroll
        for (int o = 16; o; o >>= 1) q += __shfl_down_sync(0xffffffffu, q, o);
        if (l == 0) qp[r][w] = q;
    }
    __syncthreads();
    if (tid < 8) {
        float s = 0.f;
        #pragma unroll
        for (int i = 0; i < 8; i++) s += qp[tid][i];
        g_q[spk * MUTT + part * 8 + tid] = s;
    }
    float4 s4; s4.x = c0; s4.y = c1; s4.z = c2; s4.w = c3;
    ((float4*)g_psum)[(size_t)bid * (DDIM / 4) + tid] = s4;
}

// ======================= K2: centers (fp16) ===============================
__global__ void __launch_bounds__(256) k2_center() {
    int spk = blockIdx.x, tid = threadIdx.x;
    int w = tid >> 5, l = tid & 31;
    __shared__ float wp[8];
    float4 s4 = make_float4(0.f, 0.f, 0.f, 0.f);
    #pragma unroll
    for (int p = 0; p < 8; p++) {
        float4 t = ((const float4*)g_psum)[(size_t)(spk * 8 + p) * (DDIM / 4) + tid];
        s4.x += t.x; s4.y += t.y; s4.z += t.z; s4.w += t.w;
    }
    float4 m;
    m.x = s4.x * 0.015625f; m.y = s4.y * 0.015625f;
    m.z = s4.z * 0.015625f; m.w = s4.w * 0.015625f;
    float p = m.x * m.x + m.y * m.y + m.z * m.z + m.w * m.w;
    #pragma unroll
    for (int o = 16; o; o >>= 1) p += __shfl_down_sync(0xffffffffu, p, o);
    if (l == 0) wp[w] = p;
    __syncthreads();
    float ms = 0.f;
    #pragma unroll
    for (int i = 0; i < 8; i++) ms += wp[i];
    float r = 1.f / sqrtf(fmaxf(ms, 1e-12f));

    union { __half2 h2[2]; uint2 u; } ph;
    ph.h2[0] = __floats2half2_rn(m.x * r, m.y * r);
    ph.h2[1] = __floats2half2_rn(m.z * r, m.w * r);
    *(uint2*)(g_b + (size_t)spk * DDIM + (size_t)tid * 4) = ph.u;

    if (tid == 0) {
        g_L[spk]  = 64.f * sqrtf(ms);
        g_L2[spk] = 4096.f * ms;
    }
}

// ======================= K3: fp16 HMMA GEMM, 148 variable-M CTAs ==========
// 148 CTAs; CTA i covers NT(i) row-tiles of 16 (NT = 7 for i<136 else 6).
// 8 warps: 1(M) x 8(N). BK=64 (128B/row), 3-stage ring, prefetch distance 2.
#define ROWB 144
#define NTMAX 7
#define A_OFF 0
#define B_OFF (NTMAX * 16 * ROWB)                 // 16128
#define ST_STRIDE (B_OFF + 256 * ROWB)            // 16128 + 36864 = 52992
#define K3_SMEM (3 * ST_STRIDE)                   // 158976
#define CSPLIT 136                                // CTAs with 7 tiles

static __device__ __forceinline__ void k3_loads(uint32_t sm, int st, int kst, int tid,
                                                int row0, int nrows) {
    uint32_t sb = sm + (uint32_t)st * ST_STRIDE;
    const char* ap = (const char*)g_a;
    const char* bp = (const char*)g_b;
    size_t kb = (size_t)kst * 128;  // BK=64 halves = 128 bytes within 2048-byte row
    // A: nrows x 128B -> nrows*8 chunks of 16B
    #pragma unroll
    for (int i = 0; i < 4; i++) {
        int c = tid + i * 256;
        if (c < nrows * 8) {
            int row = c >> 3; uint32_t sub = (uint32_t)(c & 7) * 16u;
            size_t go = ((size_t)(row0 + row)) * 2048 + kb + sub;
            cp16(sb + A_OFF + (uint32_t)row * ROWB + sub, ap + go);
        }
    }
    // B: 256 rows x 128B -> 2048 chunks, 8/thread
    #pragma unroll
    for (int i = 0; i < 8; i++) {
        int c = tid + i * 256;
        int row = c >> 3; uint32_t sub = (uint32_t)(c & 7) * 16u;
        size_t go = (size_t)row * 2048 + kb + sub;
        cp16(sb + B_OFF + (uint32_t)row * ROWB + sub, bp + go);
    }
}

template <int NT>
static __device__ __forceinline__ void k3_body(uint32_t sm, int tid, int row0,
                                               const float* w_p, const float* b_p,
                                               float* out) {
    int wid = tid >> 5, lane = tid & 31;
    const int nrows = NT * 16;

    // hoist scalar loads above the mainloop (ready long before epilogue)
    float W = w_p[0], Bb = b_p[0];

    uint32_t aoff[NT], boff[2];
    {
        uint32_t ars = (uint32_t)(lane & 15);
        uint32_t acs = (uint32_t)(lane >> 4) * 16u;
        uint32_t brs = (uint32_t)((lane & 7) + ((lane >> 4) << 3));
        uint32_t bcs = (uint32_t)((lane >> 3) & 1) * 16u;
        #pragma unroll
        for (int mt = 0; mt < NT; mt++)
            aoff[mt] = (uint32_t)(mt * 16 + ars) * ROWB + acs;
        #pragma unroll
        for (int np = 0; np < 2; np++)
            boff[np] = (uint32_t)(wid * 32 + np * 16 + brs) * ROWB + bcs;
    }

    float acc[NT][4][4];
    #pragma unroll
    for (int mt = 0; mt < NT; mt++)
        #pragma unroll
        for (int nt = 0; nt < 4; nt++)
            #pragma unroll
            for (int i = 0; i < 4; i++) acc[mt][nt][i] = 0.f;

    k3_loads(sm, 0, 0, tid, row0, nrows); cp_commit();
    k3_loads(sm, 1, 1, tid, row0, nrows); cp_commit();

    #pragma unroll 1
    for (int k = 0; k < 16; k++) {
        int s = k - (k / 3) * 3;              // k % 3
        if (k < 15) cp_wait<1>(); else cp_wait<0>();
        __syncthreads();
        if (k + 2 < 16) {
            int s2 = (k + 2) - ((k + 2) / 3) * 3;
            k3_loads(sm, s2, k + 2, tid, row0, nrows);
            cp_commit();
        }
        uint32_t sb = sm + (uint32_t)s * ST_STRIDE;

        #pragma unroll
        for (int ks = 0; ks < 4; ks++) {
            uint32_t kb = (uint32_t)ks * 32u;
            uint32_t a[NT][4], b[4][2];
            #pragma unroll
            for (int np = 0; np < 2; np++) {
                uint32_t t[4];
                ldsm4(t, sb + B_OFF + boff[np] + kb);
                b[2 * np][0] = t[0]; b[2 * np][1] = t[1];
                b[2 * np + 1][0] = t[2]; b[2 * np + 1][1] = t[3];
            }
            #pragma unroll
            for (int mt = 0; mt < NT; mt++)
                ldsm4(a[mt], sb + A_OFF + aoff[mt] + kb);
            #pragma unroll
            for (int mt = 0; mt < NT; mt++)
                #pragma unroll
                for (int nt = 0; nt < 4; nt++)
                    mma_f16(acc[mt][nt], a[mt], b[nt]);
        }
    }

    // ---- fused epilogue ----
    #pragma unroll
    for (int mt = 0; mt < NT; mt++) {
        int r0 = row0 + mt * 16 + (lane >> 2);
        int r1 = r0 + 8;
        int j0 = r0 >> 6, j1 = r1 >> 6;
        float q0 = g_q[r0], q1 = g_q[r1];
        float La = g_L[j0], L2a = g_L2[j0];
        float Lb = g_L[j1], L2b = g_L2[j1];
        #pragma unroll
        for (int nt = 0; nt < 4; nt++) {
            int c = wid * 32 + nt * 8 + (lane & 3) * 2;
            float v0 = acc[mt][nt][0], v1 = acc[mt][nt][1];
            float v2 = acc[mt][nt][2], v3 = acc[mt][nt][3];
            if (c == j0 || c + 1 == j0) {
                float g = (c == j0) ? v0 : v1;
                float sv = g * La;
                float dg = (sv - q0) / sqrtf(fmaxf(L2a - 2.f * sv + q0, 1e-12f));
                if (c == j0) v0 = dg; else v1 = dg;
            }
            if (c == j1 || c + 1 == j1) {
                float g = (c == j1) ? v2 : v3;
                float sv = g * Lb;
                float dg = (sv - q1) / sqrtf(fmaxf(L2b - 2.f * sv + q1, 1e-12f));
                if (c == j1) v2 = dg; else v3 = dg;
            }
            float2 o0, o1;
            o0.x = W * v0 + Bb; o0.y = W * v1 + Bb;
            o1.x = W * v2 + Bb; o1.y = W * v3 + Bb;
            *(float2*)(out + (size_t)r0 * 256 + c) = o0;
            *(float2*)(out + (size_t)r1 * 256 + c) = o1;
        }
    }
}

__global__ void __launch_bounds__(256, 1) k3_gemm(const float* __restrict__ w_p,
                                                  const float* __restrict__ b_p,
                                                  float* __restrict__ out) {
    extern __shared__ char smem[];
    uint32_t sm = smem_u32(smem);
    int tid = threadIdx.x, cta = blockIdx.x;
    if (cta < CSPLIT) {
        int row0 = cta * 112;
        k3_body<7>(sm, tid, row0, w_p, b_p, out);
    } else {
        int row0 = CSPLIT * 112 + (cta - CSPLIT) * 96;
        k3_body<6>(sm, tid, row0, w_p, b_p, out);
    }
}

// ======================= launch ===========================================
extern "C" void kernel_launch(void* const* d_in, const int* in_sizes, int n_in,
                              void* d_out, int out_size) {
    const float* in = (const float*)d_in[0];
    const float* w  = (const float*)d_in[1];
    const float* b  = (const float*)d_in[2];
    float* out = (float*)d_out;
    (void)in_sizes; (void)n_in; (void)out_size;

    cudaFuncSetAttribute(k3_gemm, cudaFuncAttributeMaxDynamicSharedMemorySize, K3_SMEM);

    k1_stats<<<NSPK * 8, 256>>>(in);
    k2_center<<<NSPK, 256>>>();
    k3_gemm<<<148, 256, K3_SMEM>>>(w, b, out);
}

// round 10
// speedup vs baseline: 1.0036x; 1.0036x over previous
#include <cuda_runtime.h>
#include <cuda_fp16.h>
#include <stdint.h>

#define NSPK 256
#define MUTT 64
#define DDIM 1024
#define NROWS (NSPK*MUTT)   // 16384

// ---------------- device scratch (no dynamic allocation allowed) ---------
__device__ __half g_a[(size_t)NROWS * DDIM];     // 32 MB  (A, fp16)
__device__ __half g_b[NSPK * DDIM];              // 512 KB (B, fp16)
__device__ float  g_psum[8 * NSPK * DDIM];       // 8 MB (8 partials/speaker)
__device__ float  g_q[NROWS];
__device__ float  g_L[NSPK];
__device__ float  g_L2[NSPK];

// ---------------- helpers -------------------------------------------------
static __device__ __forceinline__ uint32_t smem_u32(const void* p) {
    uint32_t a;
    asm("{ .reg .u64 t; cvta.to.shared.u64 t, %1; cvt.u32.u64 %0, t; }" : "=r"(a) : "l"(p));
    return a;
}
static __device__ __forceinline__ void cp16(uint32_t d, const void* s) {
    asm volatile("cp.async.cg.shared.global [%0], [%1], 16;\n" :: "r"(d), "l"(s));
}
static __device__ __forceinline__ void cp_commit() {
    asm volatile("cp.async.commit_group;\n" ::: "memory");
}
template <int N> static __device__ __forceinline__ void cp_wait() {
    asm volatile("cp.async.wait_group %0;\n" :: "n"(N) : "memory");
}
static __device__ __forceinline__ void ldsm4(uint32_t* r, uint32_t addr) {
    asm volatile("ldmatrix.sync.aligned.m8n8.x4.shared.b16 {%0,%1,%2,%3}, [%4];"
                 : "=r"(r[0]), "=r"(r[1]), "=r"(r[2]), "=r"(r[3]) : "r"(addr));
}
static __device__ __forceinline__ void mma_f16(float* d, const uint32_t* a, const uint32_t* b) {
    asm volatile("mma.sync.aligned.m16n8k16.row.col.f32.f16.f16.f32 "
                 "{%0,%1,%2,%3}, {%4,%5,%6,%7}, {%8,%9}, {%0,%1,%2,%3};"
                 : "+f"(d[0]), "+f"(d[1]), "+f"(d[2]), "+f"(d[3])
                 : "r"(a[0]), "r"(a[1]), "r"(a[2]), "r"(a[3]), "r"(b[0]), "r"(b[1]));
}

// ======================= K1: stats + fp16 A plane =========================
// 2048 blocks: 8 per speaker, 8 rows each (R7 loop form — the fastest measured).
// Streaming cache hints: input read-once (__ldcs), g_a/psum write-once (__stcs).
__global__ void __launch_bounds__(256) k1_stats(const float* __restrict__ in) {
    int bid = blockIdx.x;
    int spk = bid >> 3, part = bid & 7;
    int tid = threadIdx.x, w = tid >> 5, l = tid & 31;
    __shared__ float qp[8][8];

    float c0 = 0.f, c1 = 0.f, c2 = 0.f, c3 = 0.f;
    size_t rowbase = ((size_t)spk * MUTT + part * 8) * DDIM;
    const float4* src = (const float4*)(in + rowbase);

    #pragma unroll
    for (int r = 0; r < 8; r++) {
        float4 v = __ldcs(&src[r * (DDIM / 4) + tid]);
        c0 += v.x; c1 += v.y; c2 += v.z; c3 += v.w;
        float q = v.x * v.x + v.y * v.y + v.z * v.z + v.w * v.w;
        #pragma unroll
        for (int o = 16; o; o >>= 1) q += __shfl_down_sync(0xffffffffu, q, o);
        if (l == 0) qp[r][w] = q;

        union { __half2 h2[2]; uint2 u; } ph;
        ph.h2[0] = __floats2half2_rn(v.x, v.y);
        ph.h2[1] = __floats2half2_rn(v.z, v.w);
        __stcs((uint2*)(g_a + rowbase + (size_t)r * DDIM + (size_t)tid * 4), ph.u);
    }
    __syncthreads();
    if (tid < 8) {
        float s = 0.f;
        #pragma unroll
        for (int i = 0; i < 8; i++) s += qp[tid][i];
        g_q[spk * MUTT + part * 8 + tid] = s;
    }
    float4 s4; s4.x = c0; s4.y = c1; s4.z = c2; s4.w = c3;
    __stcs(&((float4*)g_psum)[(size_t)bid * (DDIM / 4) + tid], s4);
}

// ======================= K2: centers (fp16) ===============================
__global__ void __launch_bounds__(256) k2_center() {
    int spk = blockIdx.x, tid = threadIdx.x;
    int w = tid >> 5, l = tid & 31;
    __shared__ float wp[8];
    float4 s4 = make_float4(0.f, 0.f, 0.f, 0.f);
    #pragma unroll
    for (int p = 0; p < 8; p++) {
        float4 t = ((const float4*)g_psum)[(size_t)(spk * 8 + p) * (DDIM / 4) + tid];
        s4.x += t.x; s4.y += t.y; s4.z += t.z; s4.w += t.w;
    }
    float4 m;
    m.x = s4.x * 0.015625f; m.y = s4.y * 0.015625f;
    m.z = s4.z * 0.015625f; m.w = s4.w * 0.015625f;
    float p = m.x * m.x + m.y * m.y + m.z * m.z + m.w * m.w;
    #pragma unroll
    for (int o = 16; o; o >>= 1) p += __shfl_down_sync(0xffffffffu, p, o);
    if (l == 0) wp[w] = p;
    __syncthreads();
    float ms = 0.f;
    #pragma unroll
    for (int i = 0; i < 8; i++) ms += wp[i];
    float r = 1.f / sqrtf(fmaxf(ms, 1e-12f));

    union { __half2 h2[2]; uint2 u; } ph;
    ph.h2[0] = __floats2half2_rn(m.x * r, m.y * r);
    ph.h2[1] = __floats2half2_rn(m.z * r, m.w * r);
    *(uint2*)(g_b + (size_t)spk * DDIM + (size_t)tid * 4) = ph.u;

    if (tid == 0) {
        g_L[spk]  = 64.f * sqrtf(ms);
        g_L2[spk] = 4096.f * ms;
    }
}

// ======================= K3: fp16 HMMA GEMM, 148 variable-M CTAs ==========
// 148 CTAs; CTA i covers NT(i) row-tiles of 16 (NT = 7 for i<136 else 6).
// 8 warps: 1(M) x 8(N). BK=64 (128B/row), 3-stage ring, prefetch distance 2.
#define ROWB 144
#define NTMAX 7
#define A_OFF 0
#define B_OFF (NTMAX * 16 * ROWB)                 // 16128
#define ST_STRIDE (B_OFF + 256 * ROWB)            // 16128 + 36864 = 52992
#define K3_SMEM (3 * ST_STRIDE)                   // 158976
#define CSPLIT 136                                // CTAs with 7 tiles

static __device__ __forceinline__ void k3_loads(uint32_t sm, int st, int kst, int tid,
                                                int row0, int nrows) {
    uint32_t sb = sm + (uint32_t)st * ST_STRIDE;
    const char* ap = (const char*)g_a;
    const char* bp = (const char*)g_b;
    size_t kb = (size_t)kst * 128;  // BK=64 halves = 128 bytes within 2048-byte row
    // A: nrows x 128B -> nrows*8 chunks of 16B
    #pragma unroll
    for (int i = 0; i < 4; i++) {
        int c = tid + i * 256;
        if (c < nrows * 8) {
            int row = c >> 3; uint32_t sub = (uint32_t)(c & 7) * 16u;
            size_t go = ((size_t)(row0 + row)) * 2048 + kb + sub;
            cp16(sb + A_OFF + (uint32_t)row * ROWB + sub, ap + go);
        }
    }
    // B: 256 rows x 128B -> 2048 chunks, 8/thread
    #pragma unroll
    for (int i = 0; i < 8; i++) {
        int c = tid + i * 256;
        int row = c >> 3; uint32_t sub = (uint32_t)(c & 7) * 16u;
        size_t go = (size_t)row * 2048 + kb + sub;
        cp16(sb + B_OFF + (uint32_t)row * ROWB + sub, bp + go);
    }
}

template <int NT>
static __device__ __forceinline__ void k3_body(uint32_t sm, int tid, int row0,
                                               const float* w_p, const float* b_p,
                                               float* out) {
    int wid = tid >> 5, lane = tid & 31;
    const int nrows = NT * 16;

    uint32_t aoff[NT], boff[2];
    {
        uint32_t ars = (uint32_t)(lane & 15);
        uint32_t acs = (uint32_t)(lane >> 4) * 16u;
        uint32_t brs = (uint32_t)((lane & 7) + ((lane >> 4) << 3));
        uint32_t bcs = (uint32_t)((lane >> 3) & 1) * 16u;
        #pragma unroll
        for (int mt = 0; mt < NT; mt++)
            aoff[mt] = (uint32_t)(mt * 16 + ars) * ROWB + acs;
        #pragma unroll
        for (int np = 0; np < 2; np++)
            boff[np] = (uint32_t)(wid * 32 + np * 16 + brs) * ROWB + bcs;
    }

    float acc[NT][4][4];
    #pragma unroll
    for (int mt = 0; mt < NT; mt++)
        #pragma unroll
        for (int nt = 0; nt < 4; nt++)
            #pragma unroll
            for (int i = 0; i < 4; i++) acc[mt][nt][i] = 0.f;

    k3_loads(sm, 0, 0, tid, row0, nrows); cp_commit();
    k3_loads(sm, 1, 1, tid, row0, nrows); cp_commit();

    #pragma unroll 1
    for (int k = 0; k < 16; k++) {
        int s = k - (k / 3) * 3;              // k % 3
        if (k < 15) cp_wait<1>(); else cp_wait<0>();
        __syncthreads();
        if (k + 2 < 16) {
            int s2 = (k + 2) - ((k + 2) / 3) * 3;
            k3_loads(sm, s2, k + 2, tid, row0, nrows);
            cp_commit();
        }
        uint32_t sb = sm + (uint32_t)s * ST_STRIDE;

        #pragma unroll
        for (int ks = 0; ks < 4; ks++) {
            uint32_t kb = (uint32_t)ks * 32u;
            uint32_t a[NT][4], b[4][2];
            #pragma unroll
            for (int np = 0; np < 2; np++) {
                uint32_t t[4];
                ldsm4(t, sb + B_OFF + boff[np] + kb);
                b[2 * np][0] = t[0]; b[2 * np][1] = t[1];
                b[2 * np + 1][0] = t[2]; b[2 * np + 1][1] = t[3];
            }
            #pragma unroll
            for (int mt = 0; mt < NT; mt++)
                ldsm4(a[mt], sb + A_OFF + aoff[mt] + kb);
            #pragma unroll
            for (int mt = 0; mt < NT; mt++)
                #pragma unroll
                for (int nt = 0; nt < 4; nt++)
                    mma_f16(acc[mt][nt], a[mt], b[nt]);
        }
    }

    // ---- fused epilogue ----
    float W = w_p[0], Bb = b_p[0];
    #pragma unroll
    for (int mt = 0; mt < NT; mt++) {
        int r0 = row0 + mt * 16 + (lane >> 2);
        int r1 = r0 + 8;
        int j0 = r0 >> 6, j1 = r1 >> 6;
        float q0 = g_q[r0], q1 = g_q[r1];
        float La = g_L[j0], L2a = g_L2[j0];
        float Lb = g_L[j1], L2b = g_L2[j1];
        #pragma unroll
        for (int nt = 0; nt < 4; nt++) {
            int c = wid * 32 + nt * 8 + (lane & 3) * 2;
            float v0 = acc[mt][nt][0], v1 = acc[mt][nt][1];
            float v2 = acc[mt][nt][2], v3 = acc[mt][nt][3];
            if (c == j0 || c + 1 == j0) {
                float g = (c == j0) ? v0 : v1;
                float sv = g * La;
                float dg = (sv - q0) / sqrtf(fmaxf(L2a - 2.f * sv + q0, 1e-12f));
                if (c == j0) v0 = dg; else v1 = dg;
            }
            if (c == j1 || c + 1 == j1) {
                float g = (c == j1) ? v2 : v3;
                float sv = g * Lb;
                float dg = (sv - q1) / sqrtf(fmaxf(L2b - 2.f * sv + q1, 1e-12f));
                if (c == j1) v2 = dg; else v3 = dg;
            }
            float2 o0, o1;
            o0.x = W * v0 + Bb; o0.y = W * v1 + Bb;
            o1.x = W * v2 + Bb; o1.y = W * v3 + Bb;
            *(float2*)(out + (size_t)r0 * 256 + c) = o0;
            *(float2*)(out + (size_t)r1 * 256 + c) = o1;
        }
    }
}

__global__ void __launch_bounds__(256, 1) k3_gemm(const float* __restrict__ w_p,
                                                  const float* __restrict__ b_p,
                                                  float* __restrict__ out) {
    extern __shared__ char smem[];
    uint32_t sm = smem_u32(smem);
    int tid = threadIdx.x, cta = blockIdx.x;
    if (cta < CSPLIT) {
        int row0 = cta * 112;
        k3_body<7>(sm, tid, row0, w_p, b_p, out);
    } else {
        int row0 = CSPLIT * 112 + (cta - CSPLIT) * 96;
        k3_body<6>(sm, tid, row0, w_p, b_p, out);
    }
}

// ======================= launch ===========================================
extern "C" void kernel_launch(void* const* d_in, const int* in_sizes, int n_in,
                              void* d_out, int out_size) {
    const float* in = (const float*)d_in[0];
    const float* w  = (const float*)d_in[1];
    const float* b  = (const float*)d_in[2];
    float* out = (float*)d_out;
    (void)in_sizes; (void)n_in; (void)out_size;

    cudaFuncSetAttribute(k3_gemm, cudaFuncAttributeMaxDynamicSharedMemorySize, K3_SMEM);

    k1_stats<<<NSPK * 8, 256>>>(in);
    k2_center<<<NSPK, 256>>>();
    k3_gemm<<<148, 256, K3_SMEM>>>(w, b, out);
}

// round 11
// speedup vs baseline: 1.1833x; 1.1791x over previous
#include <cuda_runtime.h>
#include <cuda_fp16.h>
#include <stdint.h>

#define NSPK 256
#define MUTT 64
#define DDIM 1024
#define NROWS (NSPK*MUTT)   // 16384

// ---------------- device scratch (no dynamic allocation allowed) ---------
__device__ __half g_b[NSPK * DDIM];              // 512 KB (B, fp16)
__device__ float  g_psum[8 * NSPK * DDIM];       // 8 MB (8 partials/speaker)
__device__ float  g_q[NROWS];
__device__ float  g_L[NSPK];
__device__ float  g_L2[NSPK];

// ---------------- helpers -------------------------------------------------
static __device__ __forceinline__ uint32_t smem_u32(const void* p) {
    uint32_t a;
    asm("{ .reg .u64 t; cvta.to.shared.u64 t, %1; cvt.u32.u64 %0, t; }" : "=r"(a) : "l"(p));
    return a;
}
static __device__ __forceinline__ void cp16(uint32_t d, const void* s) {
    asm volatile("cp.async.cg.shared.global [%0], [%1], 16;\n" :: "r"(d), "l"(s));
}
static __device__ __forceinline__ void cp_commit() {
    asm volatile("cp.async.commit_group;\n" ::: "memory");
}
template <int N> static __device__ __forceinline__ void cp_wait() {
    asm volatile("cp.async.wait_group %0;\n" :: "n"(N) : "memory");
}
static __device__ __forceinline__ void ldsm4(uint32_t* r, uint32_t addr) {
    asm volatile("ldmatrix.sync.aligned.m8n8.x4.shared.b16 {%0,%1,%2,%3}, [%4];"
                 : "=r"(r[0]), "=r"(r[1]), "=r"(r[2]), "=r"(r[3]) : "r"(addr));
}
static __device__ __forceinline__ void mma_f16(float* d, const uint32_t* a, const uint32_t* b) {
    asm volatile("mma.sync.aligned.m16n8k16.row.col.f32.f16.f16.f32 "
                 "{%0,%1,%2,%3}, {%4,%5,%6,%7}, {%8,%9}, {%0,%1,%2,%3};"
                 : "+f"(d[0]), "+f"(d[1]), "+f"(d[2]), "+f"(d[3])
                 : "r"(a[0]), "r"(a[1]), "r"(a[2]), "r"(a[3]), "r"(b[0]), "r"(b[1]));
}
static __device__ __forceinline__ void sts64(uint32_t addr, uint32_t u0, uint32_t u1) {
    asm volatile("st.shared.v2.b32 [%0], {%1,%2};" :: "r"(addr), "r"(u0), "r"(u1));
}

// ======================= K1: stats only (no A copy) =======================
// 2048 blocks: 8 per speaker, 8 rows each. Pure read + tiny psum/q writes.
__global__ void __launch_bounds__(256) k1_stats(const float* __restrict__ in) {
    int bid = blockIdx.x;
    int spk = bid >> 3, part = bid & 7;
    int tid = threadIdx.x, w = tid >> 5, l = tid & 31;
    __shared__ float qp[8][8];

    float c0 = 0.f, c1 = 0.f, c2 = 0.f, c3 = 0.f;
    size_t rowbase = ((size_t)spk * MUTT + part * 8) * DDIM;
    const float4* src = (const float4*)(in + rowbase);

    #pragma unroll
    for (int r = 0; r < 8; r++) {
        float4 v = src[r * (DDIM / 4) + tid];
        c0 += v.x; c1 += v.y; c2 += v.z; c3 += v.w;
        float q = v.x * v.x + v.y * v.y + v.z * v.z + v.w * v.w;
        #pragma unroll
        for (int o = 16; o; o >>= 1) q += __shfl_down_sync(0xffffffffu, q, o);
        if (l == 0) qp[r][w] = q;
    }
    __syncthreads();
    if (tid < 8) {
        float s = 0.f;
        #pragma unroll
        for (int i = 0; i < 8; i++) s += qp[tid][i];
        g_q[spk * MUTT + part * 8 + tid] = s;
    }
    float4 s4; s4.x = c0; s4.y = c1; s4.z = c2; s4.w = c3;
    ((float4*)g_psum)[(size_t)bid * (DDIM / 4) + tid] = s4;
}

// ======================= K2: centers (fp16) ===============================
__global__ void __launch_bounds__(256) k2_center() {
    int spk = blockIdx.x, tid = threadIdx.x;
    int w = tid >> 5, l = tid & 31;
    __shared__ float wp[8];
    float4 s4 = make_float4(0.f, 0.f, 0.f, 0.f);
    #pragma unroll
    for (int p = 0; p < 8; p++) {
        float4 t = ((const float4*)g_psum)[(size_t)(spk * 8 + p) * (DDIM / 4) + tid];
        s4.x += t.x; s4.y += t.y; s4.z += t.z; s4.w += t.w;
    }
    float4 m;
    m.x = s4.x * 0.015625f; m.y = s4.y * 0.015625f;
    m.z = s4.z * 0.015625f; m.w = s4.w * 0.015625f;
    float p = m.x * m.x + m.y * m.y + m.z * m.z + m.w * m.w;
    #pragma unroll
    for (int o = 16; o; o >>= 1) p += __shfl_down_sync(0xffffffffu, p, o);
    if (l == 0) wp[w] = p;
    __syncthreads();
    float ms = 0.f;
    #pragma unroll
    for (int i = 0; i < 8; i++) ms += wp[i];
    float r = 1.f / sqrtf(fmaxf(ms, 1e-12f));

    union { __half2 h2[2]; uint2 u; } ph;
    ph.h2[0] = __floats2half2_rn(m.x * r, m.y * r);
    ph.h2[1] = __floats2half2_rn(m.z * r, m.w * r);
    *(uint2*)(g_b + (size_t)spk * DDIM + (size_t)tid * 4) = ph.u;

    if (tid == 0) {
        g_L[spk]  = 64.f * sqrtf(ms);
        g_L2[spk] = 4096.f * ms;
    }
}

// ======================= K3: fp16 HMMA GEMM, 148 variable-M CTAs ==========
// A is read as fp32 from the ORIGINAL input (LDG.128), converted to fp16 in
// registers, STS'd into the stage ring. B via cp.async from g_b (fp16).
// 8 warps: 1(M) x 8(N). BK=64 (128B fp16/row), 3-stage ring, distance 2.
#define ROWB 144
#define NTMAX 7
#define A_OFF 0
#define B_OFF (NTMAX * 16 * ROWB)                 // 16128
#define ST_STRIDE (B_OFF + 256 * ROWB)            // 52992
#define K3_SMEM (3 * ST_STRIDE)                   // 158976
#define CSPLIT 136                                // CTAs with 7 tiles

static __device__ __forceinline__ void k3_loadB(uint32_t sm, int st, int kst, int tid) {
    uint32_t sb = sm + (uint32_t)st * ST_STRIDE;
    const char* bp = (const char*)g_b;
    size_t kb = (size_t)kst * 128;
    #pragma unroll
    for (int i = 0; i < 8; i++) {
        int c = tid + i * 256;
        int row = c >> 3; uint32_t sub = (uint32_t)(c & 7) * 16u;
        size_t go = (size_t)row * 2048 + kb + sub;
        cp16(sb + B_OFF + (uint32_t)row * ROWB + sub, bp + go);
    }
}

// A: per-iter tile = nrows x 64 floats (256B/row fp32). 16B chunks: nrows*16.
// chunk c: row = c>>4, sub = c&15. Per thread: NT chunks.
template <int NT>
static __device__ __forceinline__ void k3_ldgA(float4* av, int kst, int tid, int row0,
                                               const float4* __restrict__ in4) {
    #pragma unroll
    for (int i = 0; i < NT; i++) {
        int c = tid + i * 256;
        int row = c >> 4, sub = c & 15;
        av[i] = in4[(size_t)(row0 + row) * 256 + kst * 16 + sub];
    }
}

template <int NT>
static __device__ __forceinline__ void k3_stsA(uint32_t sm, int st, const float4* av, int tid) {
    uint32_t sb = sm + (uint32_t)st * ST_STRIDE + A_OFF;
    #pragma unroll
    for (int i = 0; i < NT; i++) {
        int c = tid + i * 256;
        int row = c >> 4, sub = c & 15;
        __half2 h0 = __floats2half2_rn(av[i].x, av[i].y);
        __half2 h1 = __floats2half2_rn(av[i].z, av[i].w);
        sts64(sb + (uint32_t)row * ROWB + (uint32_t)sub * 8u,
              *(uint32_t*)&h0, *(uint32_t*)&h1);
    }
}

template <int NT>
static __device__ __forceinline__ void k3_body(uint32_t sm, int tid, int row0,
                                               const float4* __restrict__ in4,
                                               const float* w_p, const float* b_p,
                                               float* out) {
    int wid = tid >> 5, lane = tid & 31;

    uint32_t aoff[NT], boff[2];
    {
        uint32_t ars = (uint32_t)(lane & 15);
        uint32_t acs = (uint32_t)(lane >> 4) * 16u;
        uint32_t brs = (uint32_t)((lane & 7) + ((lane >> 4) << 3));
        uint32_t bcs = (uint32_t)((lane >> 3) & 1) * 16u;
        #pragma unroll
        for (int mt = 0; mt < NT; mt++)
            aoff[mt] = (uint32_t)(mt * 16 + ars) * ROWB + acs;
        #pragma unroll
        for (int np = 0; np < 2; np++)
            boff[np] = (uint32_t)(wid * 32 + np * 16 + brs) * ROWB + bcs;
    }

    float acc[NT][4][4];
    #pragma unroll
    for (int mt = 0; mt < NT; mt++)
        #pragma unroll
        for (int nt = 0; nt < 4; nt++)
            #pragma unroll
            for (int i = 0; i < 4; i++) acc[mt][nt][i] = 0.f;

    float4 av[NT];
    // prologue: A(0), A(1) converted into stages 0,1; B(0), B(1) via cp.async
    k3_ldgA<NT>(av, 0, tid, row0, in4);
    k3_stsA<NT>(sm, 0, av, tid);
    k3_ldgA<NT>(av, 1, tid, row0, in4);
    k3_stsA<NT>(sm, 1, av, tid);
    k3_loadB(sm, 0, 0, tid); cp_commit();
    k3_loadB(sm, 1, 1, tid); cp_commit();

    #pragma unroll 1
    for (int k = 0; k < 16; k++) {
        int s = k - (k / 3) * 3;              // k % 3
        if (k < 15) cp_wait<1>(); else cp_wait<0>();
        __syncthreads();
        int s2 = (k + 2) - ((k + 2) / 3) * 3;
        if (k + 2 < 16) {
            k3_loadB(sm, s2, k + 2, tid);     // async B prefetch
            cp_commit();
            k3_ldgA<NT>(av, k + 2, tid, row0, in4);  // LDG issues; latency hidden
        }
        uint32_t sb = sm + (uint32_t)s * ST_STRIDE;

        #pragma unroll
        for (int ks = 0; ks < 4; ks++) {
            uint32_t kb = (uint32_t)ks * 32u;
            uint32_t a[NT][4], b[4][2];
            #pragma unroll
            for (int np = 0; np < 2; np++) {
                uint32_t t[4];
                ldsm4(t, sb + B_OFF + boff[np] + kb);
                b[2 * np][0] = t[0]; b[2 * np][1] = t[1];
                b[2 * np + 1][0] = t[2]; b[2 * np + 1][1] = t[3];
            }
            #pragma unroll
            for (int mt = 0; mt < NT; mt++)
                ldsm4(a[mt], sb + A_OFF + aoff[mt] + kb);
            #pragma unroll
            for (int mt = 0; mt < NT; mt++)
                #pragma unroll
                for (int nt = 0; nt < 4; nt++)
                    mma_f16(acc[mt][nt], a[mt], b[nt]);
        }

        if (k + 2 < 16)
            k3_stsA<NT>(sm, s2, av, tid);     // convert + store after compute
    }

    // ---- fused epilogue ----
    float W = w_p[0], Bb = b_p[0];
    #pragma unroll
    for (int mt = 0; mt < NT; mt++) {
        int r0 = row0 + mt * 16 + (lane >> 2);
        int r1 = r0 + 8;
        int j0 = r0 >> 6, j1 = r1 >> 6;
        float q0 = g_q[r0], q1 = g_q[r1];
        float La = g_L[j0], L2a = g_L2[j0];
        float Lb = g_L[j1], L2b = g_L2[j1];
        #pragma unroll
        for (int nt = 0; nt < 4; nt++) {
            int c = wid * 32 + nt * 8 + (lane & 3) * 2;
            float v0 = acc[mt][nt][0], v1 = acc[mt][nt][1];
            float v2 = acc[mt][nt][2], v3 = acc[mt][nt][3];
            if (c == j0 || c + 1 == j0) {
                float g = (c == j0) ? v0 : v1;
                float sv = g * La;
                float dg = (sv - q0) / sqrtf(fmaxf(L2a - 2.f * sv + q0, 1e-12f));
                if (c == j0) v0 = dg; else v1 = dg;
            }
            if (c == j1 || c + 1 == j1) {
                float g = (c == j1) ? v2 : v3;
                float sv = g * Lb;
                float dg = (sv - q1) / sqrtf(fmaxf(L2b - 2.f * sv + q1, 1e-12f));
                if (c == j1) v2 = dg; else v3 = dg;
            }
            float2 o0, o1;
            o0.x = W * v0 + Bb; o0.y = W * v1 + Bb;
            o1.x = W * v2 + Bb; o1.y = W * v3 + Bb;
            *(float2*)(out + (size_t)r0 * 256 + c) = o0;
            *(float2*)(out + (size_t)r1 * 256 + c) = o1;
        }
    }
}

__global__ void __launch_bounds__(256, 1) k3_gemm(const float* __restrict__ in,
                                                  const float* __restrict__ w_p,
                                                  const float* __restrict__ b_p,
                                                  float* __restrict__ out) {
    extern __shared__ char smem[];
    uint32_t sm = smem_u32(smem);
    int tid = threadIdx.x, cta = blockIdx.x;
    const float4* in4 = (const float4*)in;
    if (cta < CSPLIT) {
        int row0 = cta * 112;
        k3_body<7>(sm, tid, row0, in4, w_p, b_p, out);
    } else {
        int row0 = CSPLIT * 112 + (cta - CSPLIT) * 96;
        k3_body<6>(sm, tid, row0, in4, w_p, b_p, out);
    }
}

// ======================= launch ===========================================
extern "C" void kernel_launch(void* const* d_in, const int* in_sizes, int n_in,
                              void* d_out, int out_size) {
    const float* in = (const float*)d_in[0];
    const float* w  = (const float*)d_in[1];
    const float* b  = (const float*)d_in[2];
    float* out = (float*)d_out;
    (void)in_sizes; (void)n_in; (void)out_size;

    cudaFuncSetAttribute(k3_gemm, cudaFuncAttributeMaxDynamicSharedMemorySize, K3_SMEM);

    k1_stats<<<NSPK * 8, 256>>>(in);
    k2_center<<<NSPK, 256>>>();
    k3_gemm<<<148, 256, K3_SMEM>>>(in, w, b, out);
}